// round 8
// baseline (speedup 1.0000x reference)
#include <cuda_runtime.h>
#include <stdint.h>

// =============================================================================
// key32 = int32-wrapped reference key: (b&3)<<30 | x<<20 | y<<10 | z.
// Mask table entry = 16B: .x = key<<32 | min_index, .y = float2 mask_scores
// (filled by a slot-scan pass after the CAS build). Lookup hit = ONE 16B load.
// EMPTY = 0xFFFF..F unreachable (key bit 29 always 0 for coords < 512).
// =============================================================================

#define MASK_CAP (1u << 21)   // 2.1M slots, load ~0.72, 33.5MB @ 16B
#define DS_CAP   (1u << 19)   // 4MB @ 8B
#define EMPTY64  0xFFFFFFFFFFFFFFFFull

__device__ ulonglong2         g_mtab[MASK_CAP];
__device__ unsigned long long g_dtab[DS_CAP];

__device__ __forceinline__ uint32_t key32_of(int4 c) {
    return ((uint32_t)c.x << 30) | ((uint32_t)c.y << 20) |
           ((uint32_t)c.z << 10) | (uint32_t)c.w;
}

__device__ __forceinline__ uint32_t hash32(uint32_t k) {
    k ^= k >> 16; k *= 0x85ebca6bu;
    k ^= k >> 13; k *= 0xc2b2ae35u;
    k ^= k >> 16;
    return k;
}

__device__ __forceinline__ void insert(unsigned long long* slot0, uint32_t stride,
                                       uint32_t k, int i, uint32_t capmask) {
    unsigned long long desired = ((unsigned long long)k << 32) | (uint32_t)i;
    uint32_t slot = hash32(k) & capmask;
    while (true) {
        unsigned long long* p = slot0 + (size_t)slot * stride;
        unsigned long long prev = atomicCAS(p, EMPTY64, desired);
        if (prev == EMPTY64) break;
        if ((uint32_t)(prev >> 32) == k) {    // duplicate key -> keep min index
            atomicMin(p, desired);
            break;
        }
        slot = (slot + 1) & capmask;
    }
}

// ---------------- One launch builds both tables (grid-split) ---------------
__global__ void build_all(const int4* __restrict__ mask_coords, int M,
                          const int4* __restrict__ ds_coords, int Nd,
                          int mblocks) {
    if ((int)blockIdx.x < mblocks) {
        int i = blockIdx.x * blockDim.x + threadIdx.x;
        if (i >= M) return;
        insert(&g_mtab[0].x, 2, key32_of(__ldcs(&mask_coords[i])), i, MASK_CAP - 1);
    } else {
        int i = (blockIdx.x - mblocks) * blockDim.x + threadIdx.x;
        if (i >= Nd) return;
        insert(g_dtab, 1, key32_of(__ldcs(&ds_coords[i])), i, DS_CAP - 1);
    }
}

// ---------------- Slot-scan: embed scores into occupied mask entries -------
__global__ void fill_scores(const float2* __restrict__ mask_scores) {
    int s = blockIdx.x * blockDim.x + threadIdx.x;
    if (s >= (int)MASK_CAP) return;
    unsigned long long e = g_mtab[s].x;
    if (e != EMPTY64) {
        float2 sc = __ldg(&mask_scores[(uint32_t)e]);
        unsigned long long packed;
        packed = (unsigned long long)__float_as_uint(sc.x)
               | ((unsigned long long)__float_as_uint(sc.y) << 32);
        g_mtab[s].y = packed;
    }
}

// ---------------- Fused kernel: join + all four outputs --------------------
__global__ void fused_kernel(const int4*   __restrict__ x_coords,
                             const float4* __restrict__ x_feats,
                             float4* __restrict__ pruned,
                             float4* __restrict__ scaled,
                             float*  __restrict__ merged,   // [N, C+2]
                             float*  __restrict__ ds_mask,  // [Nd]
                             int N, int VC, int C) {
    long long t = (long long)blockIdx.x * blockDim.x + threadIdx.x;
    long long total = (long long)N * VC;
    if (t >= total) return;
    int i = (int)(t / VC);          // row
    int j = (int)(t % VC);          // float4 lane within row
    int lane = threadIdx.x & 31;

    float attn = 0.0f, sc1 = 0.0f;
    if (j == 0) {
        int4 c = x_coords[i];
        uint32_t k = key32_of(c);
        float s0 = 0.0f, s1 = 0.0f;
        uint32_t slot = hash32(k) & (MASK_CAP - 1);
        while (true) {
            ulonglong2 e = __ldg(&g_mtab[slot]);
            if ((uint32_t)(e.x >> 32) == k) {      // hit: scores ride along
                s0 = __uint_as_float((uint32_t)e.y);
                s1 = __uint_as_float((uint32_t)(e.y >> 32));
                break;
            }
            if (e.x == EMPTY64) break;             // miss
            slot = (slot + 1) & (MASK_CAP - 1);
        }
        attn = (s1 > 0.5f) ? 1.0f : 0.0f;
        sc1  = s1 * attn;
        __stcs((float2*)(merged + (size_t)i * (size_t)(C + 2)),
               make_float2(s0, s1));
        if (attn > 0.0f) {
            int4 p = make_int4(c.x, c.y >> 1, c.z >> 1, c.w >> 1);
            uint32_t pk = key32_of(p);
            uint32_t ds = hash32(pk) & (DS_CAP - 1);
            while (true) {
                unsigned long long e = __ldg(&g_dtab[ds]);
                if ((uint32_t)(e >> 32) == pk) { ds_mask[(uint32_t)e] = 1.0f; break; }
                if (e == EMPTY64) break;
                ds = (ds + 1) & (DS_CAP - 1);
            }
        }
    }
    int src = lane & ~(VC - 1);     // row-leader lane (VC == 16)
    attn = __shfl_sync(0xFFFFFFFFu, attn, src);
    sc1  = __shfl_sync(0xFFFFFFFFu, sc1,  src);

    float4 f = __ldcs(&x_feats[t]);
    __stcs(&pruned[t], make_float4(f.x * attn, f.y * attn, f.z * attn, f.w * attn));
    __stcs(&scaled[t], make_float4(f.x * sc1,  f.y * sc1,  f.z * sc1,  f.w * sc1));
    float2* m = (float2*)(merged + (size_t)i * (size_t)(C + 2) + 2 + (size_t)j * 4);
    __stcs(m,     make_float2(f.x, f.y));
    __stcs(m + 1, make_float2(f.z, f.w));
}

// ---------------- Launch ----------------------------------------------------
extern "C" void kernel_launch(void* const* d_in, const int* in_sizes, int n_in,
                              void* d_out, int out_size) {
    const int4*   x_coords    = (const int4*)d_in[0];
    const float*  x_feats     = (const float*)d_in[1];
    const int4*   mask_coords = (const int4*)d_in[2];
    const float2* mask_scores = (const float2*)d_in[3];
    const int4*   ds_coords   = (const int4*)d_in[4];

    int N  = in_sizes[0] / 4;
    int C  = in_sizes[1] / N;
    int M  = in_sizes[2] / 4;
    int Nd = in_sizes[4] / 4;
    int VC = C / 4;

    float* out    = (float*)d_out;
    float* pruned = out;
    float* scaled = out + (size_t)N * C;
    float* merged = out + (size_t)2 * N * C;
    float* dsm    = merged + (size_t)N * (C + 2);

    void *mt, *dt;
    cudaGetSymbolAddress(&mt, g_mtab);
    cudaGetSymbolAddress(&dt, g_dtab);

    cudaMemsetAsync(mt, 0xFF, (size_t)MASK_CAP * sizeof(ulonglong2));
    cudaMemsetAsync(dt, 0xFF, (size_t)DS_CAP * sizeof(unsigned long long));
    cudaMemsetAsync(dsm, 0, (size_t)Nd * sizeof(float));

    const int B = 256;
    int mblocks = (M + B - 1) / B;
    int dblocks = (Nd + B - 1) / B;
    build_all<<<mblocks + dblocks, B>>>(mask_coords, M, ds_coords, Nd, mblocks);
    fill_scores<<<(MASK_CAP + B - 1) / B, B>>>(mask_scores);

    long long total = (long long)N * VC;
    int blocks = (int)((total + B - 1) / B);
    fused_kernel<<<blocks, B>>>(x_coords, (const float4*)x_feats,
                                (float4*)pruned, (float4*)scaled, merged, dsm,
                                N, VC, C);
}

// round 9
// speedup vs baseline: 1.1177x; 1.1177x over previous
#include <cuda_runtime.h>
#include <stdint.h>

// =============================================================================
// key32 = int32-wrapped reference key: (b&3)<<30 | x<<20 | y<<10 | z.
// Packed hash entry (8B): key32<<32 | index. atomicMin == min-index per key
// (stable argsort + searchsorted-left). EMPTY 0xFF..F unreachable (key bit 29
// always 0 for coords < 512).
// =============================================================================

#define MASK_CAP (1u << 22)   // load ~0.36 -> ~1.2 probes/op
#define DS_CAP   (1u << 19)
#define EMPTY64  0xFFFFFFFFFFFFFFFFull

__device__ unsigned long long g_mtab[MASK_CAP];
__device__ unsigned long long g_dtab[DS_CAP];
__device__ float2             g_rowinfo[1100000];

__device__ __forceinline__ uint32_t key32_of(int4 c) {
    return ((uint32_t)c.x << 30) | ((uint32_t)c.y << 20) |
           ((uint32_t)c.z << 10) | (uint32_t)c.w;
}

__device__ __forceinline__ uint32_t hash32(uint32_t k) {
    k ^= k >> 16; k *= 0x85ebca6bu;
    k ^= k >> 13; k *= 0xc2b2ae35u;
    k ^= k >> 16;
    return k;
}

// ---------------- One kernel clears both tables + ds output ----------------
__global__ void clear_all(float* __restrict__ dsm, int Nd) {
    int t = blockIdx.x * blockDim.x + threadIdx.x;
    int stride = gridDim.x * blockDim.x;
    ulonglong2 ff = make_ulonglong2(EMPTY64, EMPTY64);
    for (int s = t; s < (int)(MASK_CAP / 2); s += stride)
        ((ulonglong2*)g_mtab)[s] = ff;
    for (int s = t; s < (int)(DS_CAP / 2); s += stride)
        ((ulonglong2*)g_dtab)[s] = ff;
    float4 z = make_float4(0.f, 0.f, 0.f, 0.f);
    for (int s = t; s < Nd / 4; s += stride)
        ((float4*)dsm)[s] = z;
    // Nd tail (Nd may not be /4)
    int tail = (Nd / 4) * 4;
    if (t < Nd - tail) dsm[tail + t] = 0.f;
}

__device__ __forceinline__ void insert(unsigned long long* __restrict__ tab,
                                       uint32_t k, int i, uint32_t capmask) {
    unsigned long long desired = ((unsigned long long)k << 32) | (uint32_t)i;
    uint32_t slot = hash32(k) & capmask;
    while (true) {
        unsigned long long prev = atomicCAS(&tab[slot], EMPTY64, desired);
        if (prev == EMPTY64) break;
        if ((uint32_t)(prev >> 32) == k) {    // duplicate key -> keep min idx
            atomicMin(&tab[slot], desired);
            break;
        }
        slot = (slot + 1) & capmask;
    }
}

// ---------------- Build both tables, 4 strided items per thread ------------
__global__ void build_all(const int4* __restrict__ mask_coords, int M,
                          const int4* __restrict__ ds_coords, int Nd) {
    int t = blockIdx.x * blockDim.x + threadIdx.x;
    int stride = gridDim.x * blockDim.x;
    int W = M + Nd;
    for (int it = t; it < W; it += stride) {
        if (it < M)
            insert(g_mtab, key32_of(__ldcs(&mask_coords[it])), it, MASK_CAP - 1);
        else
            insert(g_dtab, key32_of(__ldcs(&ds_coords[it - M])), it - M,
                   DS_CAP - 1);
    }
}

// ---------------- Row kernel: join + merged[:,0:2] + ds scatter ------------
__global__ void row_kernel(const int4* __restrict__ x_coords,
                           const float2* __restrict__ mask_scores,
                           float* __restrict__ merged,   // [N, C+2]
                           float* __restrict__ ds_mask,  // [Nd]
                           int N, int C) {
    int i = blockIdx.x * blockDim.x + threadIdx.x;
    if (i >= N) return;
    int4 c = x_coords[i];
    uint32_t k = key32_of(c);
    float s0 = 0.0f, s1 = 0.0f;
    uint32_t slot = hash32(k) & (MASK_CAP - 1);
    while (true) {
        unsigned long long e = __ldg(&g_mtab[slot]);
        if ((uint32_t)(e >> 32) == k) {
            float2 msv = __ldg(&mask_scores[(uint32_t)e]);
            s0 = msv.x; s1 = msv.y;
            break;
        }
        if (e == EMPTY64) break;
        slot = (slot + 1) & (MASK_CAP - 1);
    }
    float attn = (s1 > 0.5f) ? 1.0f : 0.0f;
    g_rowinfo[i] = make_float2(attn, s1 * attn);
    __stcs((float2*)(merged + (size_t)i * (size_t)(C + 2)), make_float2(s0, s1));
    if (attn > 0.0f) {
        int4 p = make_int4(c.x, c.y >> 1, c.z >> 1, c.w >> 1);
        uint32_t pk = key32_of(p);
        uint32_t ds = hash32(pk) & (DS_CAP - 1);
        while (true) {
            unsigned long long e = __ldg(&g_dtab[ds]);
            if ((uint32_t)(e >> 32) == pk) { ds_mask[(uint32_t)e] = 1.0f; break; }
            if (e == EMPTY64) break;
            ds = (ds + 1) & (DS_CAP - 1);
        }
    }
}

// ---------------- Feature kernel: clean float4 stream ----------------------
__global__ void feat_kernel(const float4* __restrict__ x_feats,
                            float4* __restrict__ pruned,
                            float4* __restrict__ scaled,
                            float* __restrict__ merged,
                            int N, int VC, int C) {
    long long t = (long long)blockIdx.x * blockDim.x + threadIdx.x;
    long long total = (long long)N * VC;
    if (t >= total) return;
    int i = (int)(t / VC);
    int j = (int)(t % VC);
    float4 f = __ldcs(&x_feats[t]);
    float2 rs = g_rowinfo[i];
    __stcs(&pruned[t], make_float4(f.x * rs.x, f.y * rs.x, f.z * rs.x, f.w * rs.x));
    __stcs(&scaled[t], make_float4(f.x * rs.y, f.y * rs.y, f.z * rs.y, f.w * rs.y));
    float2* m = (float2*)(merged + (size_t)i * (size_t)(C + 2) + 2 + (size_t)j * 4);
    __stcs(m,     make_float2(f.x, f.y));
    __stcs(m + 1, make_float2(f.z, f.w));
}

// ---------------- Launch ----------------------------------------------------
extern "C" void kernel_launch(void* const* d_in, const int* in_sizes, int n_in,
                              void* d_out, int out_size) {
    const int4*   x_coords    = (const int4*)d_in[0];
    const float*  x_feats     = (const float*)d_in[1];
    const int4*   mask_coords = (const int4*)d_in[2];
    const float2* mask_scores = (const float2*)d_in[3];
    const int4*   ds_coords   = (const int4*)d_in[4];

    int N  = in_sizes[0] / 4;
    int C  = in_sizes[1] / N;
    int M  = in_sizes[2] / 4;
    int Nd = in_sizes[4] / 4;
    int VC = C / 4;

    float* out    = (float*)d_out;
    float* pruned = out;
    float* scaled = out + (size_t)N * C;
    float* merged = out + (size_t)2 * N * C;
    float* dsm    = merged + (size_t)N * (C + 2);

    const int B = 256;
    clear_all<<<592, B>>>(dsm, Nd);   // 4 waves of 148 SMs, grid-stride

    int W = M + Nd;
    int bblocks = (W + B * 4 - 1) / (B * 4);
    build_all<<<bblocks, B>>>(mask_coords, M, ds_coords, Nd);

    row_kernel<<<(N + B - 1) / B, B>>>(x_coords, mask_scores, merged, dsm, N, C);

    long long total = (long long)N * VC;
    int blocks = (int)((total + B - 1) / B);
    feat_kernel<<<blocks, B>>>((const float4*)x_feats, (float4*)pruned,
                               (float4*)scaled, merged, N, VC, C);
}

// round 10
// speedup vs baseline: 1.3262x; 1.1866x over previous
#include <cuda_runtime.h>
#include <stdint.h>

// =============================================================================
// key32 = int32-wrapped reference key: (b&3)<<30 | x<<20 | y<<10 | z.
// Packed hash entry (8B): key32<<32 | index. atomicMin == min-index per key
// (stable argsort + searchsorted-left). EMPTY 0xFF..F unreachable (key bit 29
// always 0 for coords < 512).
// Measured per-phase bests this session:
//   clear (1 kernel)            ~6us
//   build 8B entries, 1 thr/item 31us   (16B entries or multi-insert: 70-93us)
//   row join standalone          ~25us
//   feat plain stores           170us @ 74.7% DRAM  (.cs hints: 197us @ 65%)
// =============================================================================

#define MASK_CAP (1u << 22)   // load ~0.36 -> ~1.2 probes/op
#define DS_CAP   (1u << 19)
#define EMPTY64  0xFFFFFFFFFFFFFFFFull

__device__ unsigned long long g_mtab[MASK_CAP];
__device__ unsigned long long g_dtab[DS_CAP];
__device__ float2             g_rowinfo[1100000];

__device__ __forceinline__ uint32_t key32_of(int4 c) {
    return ((uint32_t)c.x << 30) | ((uint32_t)c.y << 20) |
           ((uint32_t)c.z << 10) | (uint32_t)c.w;
}

__device__ __forceinline__ uint32_t hash32(uint32_t k) {
    k ^= k >> 16; k *= 0x85ebca6bu;
    k ^= k >> 13; k *= 0xc2b2ae35u;
    k ^= k >> 16;
    return k;
}

// ---------------- One kernel clears both tables + ds output ----------------
__global__ void clear_all(float* __restrict__ dsm, int Nd) {
    int t = blockIdx.x * blockDim.x + threadIdx.x;
    int stride = gridDim.x * blockDim.x;
    ulonglong2 ff = make_ulonglong2(EMPTY64, EMPTY64);
    for (int s = t; s < (int)(MASK_CAP / 2); s += stride)
        ((ulonglong2*)g_mtab)[s] = ff;
    for (int s = t; s < (int)(DS_CAP / 2); s += stride)
        ((ulonglong2*)g_dtab)[s] = ff;
    float4 z = make_float4(0.f, 0.f, 0.f, 0.f);
    for (int s = t; s < Nd / 4; s += stride)
        ((float4*)dsm)[s] = z;
    int tail = (Nd / 4) * 4;
    if (t < Nd - tail) dsm[tail + t] = 0.f;
}

__device__ __forceinline__ void insert(unsigned long long* __restrict__ tab,
                                       uint32_t k, int i, uint32_t capmask) {
    unsigned long long desired = ((unsigned long long)k << 32) | (uint32_t)i;
    uint32_t slot = hash32(k) & capmask;
    while (true) {
        unsigned long long prev = atomicCAS(&tab[slot], EMPTY64, desired);
        if (prev == EMPTY64) break;
        if ((uint32_t)(prev >> 32) == k) {    // duplicate key -> keep min idx
            atomicMin(&tab[slot], desired);
            break;
        }
        slot = (slot + 1) & capmask;
    }
}

// ---------------- Build both tables: ONE launch, one item per thread -------
__global__ void build_all(const int4* __restrict__ mask_coords, int M,
                          const int4* __restrict__ ds_coords, int Nd,
                          int mblocks) {
    if ((int)blockIdx.x < mblocks) {
        int i = blockIdx.x * blockDim.x + threadIdx.x;
        if (i >= M) return;
        insert(g_mtab, key32_of(mask_coords[i]), i, MASK_CAP - 1);
    } else {
        int i = (blockIdx.x - mblocks) * blockDim.x + threadIdx.x;
        if (i >= Nd) return;
        insert(g_dtab, key32_of(ds_coords[i]), i, DS_CAP - 1);
    }
}

// ---------------- Row kernel: join + merged[:,0:2] + ds scatter ------------
__global__ void row_kernel(const int4* __restrict__ x_coords,
                           const float2* __restrict__ mask_scores,
                           float* __restrict__ merged,   // [N, C+2]
                           float* __restrict__ ds_mask,  // [Nd]
                           int N, int C) {
    int i = blockIdx.x * blockDim.x + threadIdx.x;
    if (i >= N) return;
    int4 c = x_coords[i];
    uint32_t k = key32_of(c);
    float s0 = 0.0f, s1 = 0.0f;
    uint32_t slot = hash32(k) & (MASK_CAP - 1);
    while (true) {
        unsigned long long e = __ldg(&g_mtab[slot]);
        if ((uint32_t)(e >> 32) == k) {
            float2 msv = __ldg(&mask_scores[(uint32_t)e]);
            s0 = msv.x; s1 = msv.y;
            break;
        }
        if (e == EMPTY64) break;
        slot = (slot + 1) & (MASK_CAP - 1);
    }
    float attn = (s1 > 0.5f) ? 1.0f : 0.0f;
    g_rowinfo[i] = make_float2(attn, s1 * attn);
    *(float2*)(merged + (size_t)i * (size_t)(C + 2)) = make_float2(s0, s1);
    if (attn > 0.0f) {
        int4 p = make_int4(c.x, c.y >> 1, c.z >> 1, c.w >> 1);
        uint32_t pk = key32_of(p);
        uint32_t ds = hash32(pk) & (DS_CAP - 1);
        while (true) {
            unsigned long long e = __ldg(&g_dtab[ds]);
            if ((uint32_t)(e >> 32) == pk) { ds_mask[(uint32_t)e] = 1.0f; break; }
            if (e == EMPTY64) break;
            ds = (ds + 1) & (DS_CAP - 1);
        }
    }
}

// ---------------- Feature kernel: clean float4 stream, PLAIN stores --------
__global__ void feat_kernel(const float4* __restrict__ x_feats,
                            float4* __restrict__ pruned,
                            float4* __restrict__ scaled,
                            float* __restrict__ merged,
                            int N, int VC, int C) {
    long long t = (long long)blockIdx.x * blockDim.x + threadIdx.x;
    long long total = (long long)N * VC;
    if (t >= total) return;
    int i = (int)(t / VC);
    int j = (int)(t % VC);
    float4 f = x_feats[t];
    float2 rs = g_rowinfo[i];
    pruned[t] = make_float4(f.x * rs.x, f.y * rs.x, f.z * rs.x, f.w * rs.x);
    scaled[t] = make_float4(f.x * rs.y, f.y * rs.y, f.z * rs.y, f.w * rs.y);
    float2* m = (float2*)(merged + (size_t)i * (size_t)(C + 2) + 2 + (size_t)j * 4);
    m[0] = make_float2(f.x, f.y);
    m[1] = make_float2(f.z, f.w);
}

// ---------------- Launch ----------------------------------------------------
extern "C" void kernel_launch(void* const* d_in, const int* in_sizes, int n_in,
                              void* d_out, int out_size) {
    const int4*   x_coords    = (const int4*)d_in[0];
    const float*  x_feats     = (const float*)d_in[1];
    const int4*   mask_coords = (const int4*)d_in[2];
    const float2* mask_scores = (const float2*)d_in[3];
    const int4*   ds_coords   = (const int4*)d_in[4];

    int N  = in_sizes[0] / 4;
    int C  = in_sizes[1] / N;
    int M  = in_sizes[2] / 4;
    int Nd = in_sizes[4] / 4;
    int VC = C / 4;

    float* out    = (float*)d_out;
    float* pruned = out;
    float* scaled = out + (size_t)N * C;
    float* merged = out + (size_t)2 * N * C;
    float* dsm    = merged + (size_t)N * (C + 2);

    const int B = 256;
    clear_all<<<592, B>>>(dsm, Nd);

    int mblocks = (M + B - 1) / B;
    int dblocks = (Nd + B - 1) / B;
    build_all<<<mblocks + dblocks, B>>>(mask_coords, M, ds_coords, Nd, mblocks);

    row_kernel<<<(N + B - 1) / B, B>>>(x_coords, mask_scores, merged, dsm, N, C);

    long long total = (long long)N * VC;
    int blocks = (int)((total + B - 1) / B);
    feat_kernel<<<blocks, B>>>((const float4*)x_feats, (float4*)pruned,
                               (float4*)scaled, merged, N, VC, C);
}